// round 15
// baseline (speedup 1.0000x reference)
#include <cuda_runtime.h>
#include <cuda_fp16.h>
#include <cstdint>
#include <cstddef>

#define NB 4096
#define NT 48
#define NI 128
#define NH 512
#define NROWS (NT*NB)   // 196608

// ---------------- static scratch (allocation-free rule) ----------------
__device__ __half g_D16 [(size_t)NROWS*NI];
__device__ __half g_XM16[(size_t)NROWS*NI];
__device__ __half g_WtdT[NI*NH];
__device__ __half g_U16 [NI*NH];
__device__ __half g_Wh16[NH*NH];
__device__ __half g_G16 [(size_t)NROWS*NH];
__device__ __half g_Z16 [(size_t)NROWS*NH];
__device__ __half g_stage[(size_t)2*32*128*NH];   // double-buffered h*gamma exchange

// ---------------- PTX helpers (sm_103 baseline features only) ----------------
__device__ __forceinline__ void cp16(uint32_t s, const void* g) {
    asm volatile("cp.async.cg.shared.global [%0], [%1], 16;\n" :: "r"(s), "l"(g));
}
__device__ __forceinline__ void cpcommit() { asm volatile("cp.async.commit_group;\n" ::: "memory"); }

__device__ __forceinline__ void ldm4(uint32_t* d, uint32_t a) {
    asm volatile("ldmatrix.sync.aligned.m8n8.x4.shared.b16 {%0,%1,%2,%3}, [%4];\n"
        : "=r"(d[0]), "=r"(d[1]), "=r"(d[2]), "=r"(d[3]) : "r"(a));
}
__device__ __forceinline__ void ldm4t(uint32_t* d, uint32_t a) {
    asm volatile("ldmatrix.sync.aligned.m8n8.x4.trans.shared.b16 {%0,%1,%2,%3}, [%4];\n"
        : "=r"(d[0]), "=r"(d[1]), "=r"(d[2]), "=r"(d[3]) : "r"(a));
}
__device__ __forceinline__ void mma16816(float* c, const uint32_t* a, uint32_t b0, uint32_t b1) {
    asm volatile("mma.sync.aligned.m16n8k16.row.col.f32.f16.f16.f32 "
        "{%0,%1,%2,%3}, {%4,%5,%6,%7}, {%8,%9}, {%0,%1,%2,%3};\n"
        : "+f"(c[0]), "+f"(c[1]), "+f"(c[2]), "+f"(c[3])
        : "r"(a[0]), "r"(a[1]), "r"(a[2]), "r"(a[3]), "r"(b0), "r"(b1));
}
#define CARRIVE() asm volatile("barrier.cluster.arrive.aligned;" ::: "memory")
#define CWAIT()   asm volatile("barrier.cluster.wait.aligned;"   ::: "memory")

// ---------------- weight conversion ----------------
__global__ void convert_weights(const float* __restrict__ Wtd, const float* __restrict__ Wh,
                                const float* __restrict__ Uh) {
    int idx = blockIdx.x*blockDim.x + threadIdx.x;
    if (idx < NI*NH) {
        int i = idx / NH, j = idx % NH;
        g_WtdT[idx] = __float2half_rn(Wtd[j*NI + i]);
        g_U16[idx]  = __float2half_rn(Uh[idx]);
    }
    if (idx < NH*NH) g_Wh16[idx] = __float2half_rn(Wh[idx]);
}

// ---------------- D scan + masked x ----------------
__global__ void dscan_kernel(const float* __restrict__ X, const float* __restrict__ M) {
    int idx = blockIdx.x*blockDim.x + threadIdx.x;
    int b = idx >> 7, i = idx & 127;
    const float* Xp = X + (size_t)b*NT*NI + i;
    const float* Mp = M + (size_t)b*NT*NI + i;
    size_t o = (size_t)b*NI + i;
    float d = 0.f;
    #pragma unroll 1
    for (int t = 0; t < NT; t++) {
        g_D16[(size_t)t*NB*NI + o] = __float2half_rn(d);
        float m = Mp[(size_t)t*NI];
        float x = Xp[(size_t)t*NI];
        g_XM16[(size_t)t*NB*NI + o] = __float2half_rn(m*x);
        d = 1.f + ((m != 1.f) ? d : 0.f);
    }
}

// ---------------- precompute GEMM: B-persistent, 4 m-blocks per CTA ----------------
#define PRE_SMEM 98304
__global__ __launch_bounds__(256) void pregemm_kernel(const float* __restrict__ b_td,
                                                      const float* __restrict__ b_h) {
    extern __shared__ __half smem[];
    const int tid = threadIdx.x, lane = tid & 31, warp = tid >> 5;
    const int wm = warp & 1, wn = warp >> 1;
    const int n0 = blockIdx.x * 128;
    int yy = blockIdx.y;
    const bool isZ = yy >= (NROWS/128/4);
    if (isZ) yy -= (NROWS/128/4);
    // gamma rows for t=0 multiply h_0 = 0 — never read. Skip those CTAs.
    if (!isZ && yy < 8) return;
    const int base = yy * 4;
    const __half* A  = isZ ? g_XM16 : g_D16;
    const __half* Bm = isZ ? g_U16  : g_WtdT;
    const float* bias = isZ ? b_h : b_td;

    uint32_t sB  = (uint32_t)__cvta_generic_to_shared(smem);
    uint32_t sA0 = sB + 32768;

    #pragma unroll
    for (int p = 0; p < 8; p++) {
        int idx = tid + p*256;
        int r = idx >> 4, c = idx & 15;
        cp16(sB + (uint32_t)(r*16 + (c ^ (r & 7)))*16, Bm + (size_t)r*NH + n0 + c*8);
    }
    cpcommit();
    #pragma unroll
    for (int j = 0; j < 2; j++) {
        int row0 = (base + j) * 128;
        #pragma unroll
        for (int p = 0; p < 8; p++) {
            int idx = tid + p*256;
            int r = idx >> 4, c = idx & 15;
            cp16(sA0 + (uint32_t)(j*32768) + (uint32_t)(r*16 + (c ^ (r & 7)))*16,
                 A + (size_t)(row0 + r)*NI + c*8);
        }
        cpcommit();
    }

    #pragma unroll 1
    for (int mb = 0; mb < 4; mb++) {
        const int row0 = (base + mb) * 128;
        if (mb < 3) asm volatile("cp.async.wait_group 1;" ::: "memory");
        else        asm volatile("cp.async.wait_group 0;" ::: "memory");
        __syncthreads();
        uint32_t sA = sA0 + (uint32_t)((mb & 1)*32768);

        float acc[4][4][4];
        #pragma unroll
        for (int mt = 0; mt < 4; mt++)
            #pragma unroll
            for (int nt = 0; nt < 4; nt++)
                #pragma unroll
                for (int q = 0; q < 4; q++) acc[mt][nt][q] = 0.f;

        #pragma unroll
        for (int kk = 0; kk < 8; kk++) {
            uint32_t a[4][4];
            #pragma unroll
            for (int mt = 0; mt < 4; mt++) {
                int r = wm*64 + mt*16 + (lane & 15);
                int c = kk*2 + (lane >> 4);
                ldm4(a[mt], sA + (uint32_t)(r*16 + (c ^ (r & 7)))*16);
            }
            uint32_t bf[2][4];
            #pragma unroll
            for (int n2 = 0; n2 < 2; n2++) {
                int g = lane >> 3;
                int r = kk*16 + (g & 1)*8 + (lane & 7);
                int c = wn*4 + n2*2 + (g >> 1);
                ldm4t(bf[n2], sB + (uint32_t)(r*16 + (c ^ (r & 7)))*16);
            }
            #pragma unroll
            for (int mt = 0; mt < 4; mt++)
                #pragma unroll
                for (int nt = 0; nt < 4; nt++)
                    mma16816(acc[mt][nt], a[mt], bf[nt>>1][(nt&1)*2], bf[nt>>1][(nt&1)*2+1]);
        }
        __syncthreads();

        if (mb + 2 < 4) {
            int row2 = (base + mb + 2) * 128;
            #pragma unroll
            for (int p = 0; p < 8; p++) {
                int idx = tid + p*256;
                int r = idx >> 4, c = idx & 15;
                cp16(sA + (uint32_t)(r*16 + (c ^ (r & 7)))*16,
                     A + (size_t)(row2 + r)*NI + c*8);
            }
            cpcommit();
        }

        #pragma unroll
        for (int mt = 0; mt < 4; mt++) {
            #pragma unroll
            for (int nt = 0; nt < 4; nt++) {
                int col = n0 + wn*32 + nt*8 + (lane & 3)*2;
                float bv0 = bias[col], bv1 = bias[col+1];
                #pragma unroll
                for (int hh = 0; hh < 2; hh++) {
                    int r = row0 + wm*64 + mt*16 + (lane >> 2) + hh*8;
                    float v0 = acc[mt][nt][hh*2+0] + bv0;
                    float v1 = acc[mt][nt][hh*2+1] + bv1;
                    if (!isZ) {
                        v0 = __expf(-fmaxf(v0, 0.f));
                        v1 = __expf(-fmaxf(v1, 0.f));
                        *reinterpret_cast<__half2*>(&g_G16[(size_t)r*NH + col]) = __floats2half2_rn(v0, v1);
                    } else {
                        *reinterpret_cast<__half2*>(&g_Z16[(size_t)r*NH + col]) = __floats2half2_rn(v0, v1);
                    }
                }
            }
        }
    }
}

// ---------------- recurrent kernel: 128 thr / 4 warps, 64x64 warp tiles ----------------
// Fragment traffic 512KB/step (was 768KB @ 8 warps). R13 skeleton otherwise.
#define SZ_ROW 272
#define REC_SMEM (131072 + 65536 + 128*SZ_ROW)   // 231424

__global__ __launch_bounds__(128, 1) __cluster_dims__(4, 1, 1)
void rec_kernel(float* __restrict__ out) {
    extern __shared__ __half smem[];
    uint32_t sW = (uint32_t)__cvta_generic_to_shared(smem);   // [512][16 chunks] swizzled
    uint32_t sA = sW + 131072;                                // 4 stages x [128][8 chunks]
    uint32_t sZ = sW + 131072 + 65536;                        // [128][272B]

    const int tid = threadIdx.x, lane = tid & 31, warp = tid >> 5;
    const int wm = warp & 1, wn = warp >> 1;      // 2 rowg(64) x 2 colg(64)
    uint32_t rank; asm("mov.u32 %0, %%cluster_ctarank;" : "=r"(rank));
    const int cl = blockIdx.x >> 2;
    const int b0 = cl * 128;
    const int n_base = (int)rank * 128;

    // resident W (8192 chunks)
    #pragma unroll
    for (int p = 0; p < 64; p++) {
        int idx = tid + p*128;
        int r = idx >> 4, c = idx & 15;
        cp16(sW + (uint32_t)(r*16 + (c ^ (r & 7)))*16,
             g_Wh16 + (size_t)r*NH + n_base + c*8);
    }
    cpcommit();
    asm volatile("cp.async.wait_group 0;" ::: "memory");
    __syncthreads();

    #pragma unroll 1
    for (int t = 0; t < NT; t++) {
        float acc[4][8][4];
        #pragma unroll
        for (int mt = 0; mt < 4; mt++)
            #pragma unroll
            for (int nt = 0; nt < 8; nt++)
                #pragma unroll
                for (int q = 0; q < 4; q++) acc[mt][nt][q] = 0.f;

        if (t) {
            const __half* stg = g_stage + ((size_t)(t & 1)*32 + cl)*128*NH;

            // prefetch A slabs 0..2 (1024 chunks each)
            #pragma unroll
            for (int j = 0; j < 3; j++) {
                #pragma unroll
                for (int p = 0; p < 8; p++) {
                    int idx = tid + p*128;
                    int r = idx >> 3, c = idx & 7;
                    cp16(sA + (uint32_t)(j*16384) + (uint32_t)(r*8 + (c ^ (r & 7)))*16,
                         stg + (size_t)r*NH + j*64 + c*8);
                }
                cpcommit();
            }
            // prefetch Z[t] (2048 chunks)
            {
                const __half* zsrc = g_Z16 + ((size_t)t*NB + b0)*NH + n_base;
                #pragma unroll
                for (int p = 0; p < 16; p++) {
                    int idx = tid + p*128;
                    int r = idx >> 4, c = idx & 15;
                    cp16(sZ + (uint32_t)(r*SZ_ROW + c*16), zsrc + (size_t)r*NH + c*8);
                }
                cpcommit();
            }

            #pragma unroll
            for (int s = 0; s < 8; s++) {
                if (s < 3)       asm volatile("cp.async.wait_group 3;" ::: "memory");
                else if (s < 6)  asm volatile("cp.async.wait_group 2;" ::: "memory");
                else if (s == 6) asm volatile("cp.async.wait_group 1;" ::: "memory");
                else             asm volatile("cp.async.wait_group 0;" ::: "memory");
                __syncthreads();
                if (s < 5) {                 // refill slab s+3 into stage (s+3)&3
                    int j = s + 3;
                    #pragma unroll
                    for (int p = 0; p < 8; p++) {
                        int idx = tid + p*128;
                        int r = idx >> 3, c = idx & 7;
                        cp16(sA + (uint32_t)((j & 3)*16384) + (uint32_t)(r*8 + (c ^ (r & 7)))*16,
                             stg + (size_t)r*NH + j*64 + c*8);
                    }
                    cpcommit();
                }
                uint32_t bufA = sA + (uint32_t)((s & 3)*16384);
                // batched k16-pairs: 16 LDSMs back-to-back, then 64 MMAs
                #pragma unroll
                for (int kp = 0; kp < 2; kp++) {
                    uint32_t a[2][4][4];
                    uint32_t bf[2][4][4];
                    #pragma unroll
                    for (int kq = 0; kq < 2; kq++) {
                        int k16 = kp*2 + kq;
                        #pragma unroll
                        for (int mt = 0; mt < 4; mt++) {
                            int r = wm*64 + mt*16 + (lane & 15);
                            int c = k16*2 + (lane >> 4);
                            ldm4(a[kq][mt], bufA + (uint32_t)(r*8 + (c ^ (r & 7)))*16);
                        }
                        int gq = lane >> 3;
                        #pragma unroll
                        for (int n2 = 0; n2 < 4; n2++) {
                            int rr = s*64 + k16*16 + (gq & 1)*8 + (lane & 7);
                            int c = wn*8 + n2*2 + (gq >> 1);
                            ldm4t(bf[kq][n2], sW + (uint32_t)(rr*16 + (c ^ (rr & 7)))*16);
                        }
                    }
                    #pragma unroll
                    for (int kq = 0; kq < 2; kq++)
                        #pragma unroll
                        for (int mt = 0; mt < 4; mt++)
                            #pragma unroll
                            for (int nt = 0; nt < 8; nt++)
                                mma16816(acc[mt][nt], a[kq][mt],
                                         bf[kq][nt>>1][(nt&1)*2], bf[kq][nt>>1][(nt&1)*2+1]);
                }
            }
        } else {
            // t==0: only Z prefetch
            const __half* zsrc = g_Z16 + ((size_t)b0)*NH + n_base;
            #pragma unroll
            for (int p = 0; p < 16; p++) {
                int idx = tid + p*128;
                int r = idx >> 4, c = idx & 15;
                cp16(sZ + (uint32_t)(r*SZ_ROW + c*16), zsrc + (size_t)r*NH + c*8);
            }
            cpcommit();
            asm volatile("cp.async.wait_group 0;" ::: "memory");
            __syncthreads();
        }

        // ---- epilogue: h = sigmoid(acc + Z_smem); STG out; STS h*gamma into sZ ----
        // G[t+1] loaded per-mt chunk (16 regs live) to stay under the register budget.
        #pragma unroll
        for (int mt = 0; mt < 4; mt++) {
            uint32_t greg[8][2];
            if (t + 1 < NT) {
                #pragma unroll
                for (int hh = 0; hh < 2; hh++) {
                    int row = wm*64 + mt*16 + (lane >> 2) + hh*8;
                    size_t grow = ((size_t)(t+1)*NB + b0 + row)*NH;
                    #pragma unroll
                    for (int nt = 0; nt < 8; nt++) {
                        int gcol = n_base + wn*64 + nt*8 + (lane & 3)*2;
                        greg[nt][hh] =
                            __ldg(reinterpret_cast<const uint32_t*>(&g_G16[grow + gcol]));
                    }
                }
            }
            #pragma unroll
            for (int hh = 0; hh < 2; hh++) {
                int row = wm*64 + mt*16 + (lane >> 2) + hh*8;
                size_t orow = ((size_t)(b0 + row)*NT + t)*NH;
                #pragma unroll
                for (int nt = 0; nt < 8; nt++) {
                    int col = wn*64 + nt*8 + (lane & 3)*2;      // local col (0..127)
                    uint32_t zaddr = sZ + (uint32_t)(row*SZ_ROW + col*2);
                    uint32_t zu;
                    asm volatile("ld.shared.b32 %0, [%1];" : "=r"(zu) : "r"(zaddr));
                    float2 z = __half22float2(*reinterpret_cast<__half2*>(&zu));
                    float s0 = acc[mt][nt][hh*2+0] + z.x;
                    float s1 = acc[mt][nt][hh*2+1] + z.y;
                    float t0, t1;
                    asm("tanh.approx.f32 %0, %1;" : "=f"(t0) : "f"(s0*0.5f));
                    asm("tanh.approx.f32 %0, %1;" : "=f"(t1) : "f"(s1*0.5f));
                    float h0 = fmaf(0.5f, t0, 0.5f);
                    float h1 = fmaf(0.5f, t1, 0.5f);
                    *reinterpret_cast<float2*>(&out[orow + n_base + col]) = make_float2(h0, h1);
                    if (t + 1 < NT) {
                        uint32_t gu = greg[nt][hh];
                        float2 gf = __half22float2(*reinterpret_cast<__half2*>(&gu));
                        __half2 v = __floats2half2_rn(h0*gf.x, h1*gf.y);
                        asm volatile("st.shared.b32 [%0], %1;"
                                     :: "r"(zaddr), "r"(*reinterpret_cast<uint32_t*>(&v)));
                    }
                }
            }
        }

        if (t + 1 < NT) {
            __syncthreads();   // all STS visible
            // coalesced copy sZ -> stage[(t+1)&1] (2048 x 16B)
            __half* stw = g_stage + ((size_t)((t + 1) & 1)*32 + cl)*128*NH + n_base;
            #pragma unroll
            for (int p = 0; p < 16; p++) {
                int chunk = tid + p*128;
                int r = chunk >> 4, c = chunk & 15;
                uint4 v;
                asm volatile("ld.shared.v4.b32 {%0,%1,%2,%3}, [%4];"
                    : "=r"(v.x), "=r"(v.y), "=r"(v.z), "=r"(v.w)
                    : "r"(sZ + (uint32_t)(r*SZ_ROW + c*16)));
                __stcg(reinterpret_cast<uint4*>(&stw[(size_t)r*NH + c*8]), v);
            }
            CARRIVE();
            CWAIT();
        }
        __syncthreads();
    }
}

// ---------------- launch ----------------
extern "C" void kernel_launch(void* const* d_in, const int* in_sizes, int n_in,
                              void* d_out, int out_size) {
    const float* X   = (const float*)d_in[0];
    const float* M   = (const float*)d_in[1];
    const float* Wtd = (const float*)d_in[2];
    const float* btd = (const float*)d_in[3];
    // d_in[4] = W_hr, d_in[5] = b_hr : provably dead (m binary => x_c*m == m*x)
    const float* Wh  = (const float*)d_in[6];
    const float* Uh  = (const float*)d_in[7];
    const float* bh  = (const float*)d_in[8];
    float* out = (float*)d_out;

    cudaFuncSetAttribute(pregemm_kernel, cudaFuncAttributeMaxDynamicSharedMemorySize, PRE_SMEM);
    cudaFuncSetAttribute(rec_kernel,     cudaFuncAttributeMaxDynamicSharedMemorySize, REC_SMEM);

    convert_weights<<<1024, 256>>>(Wtd, Wh, Uh);
    dscan_kernel<<<(NB*NI)/256, 256>>>(X, M);
    pregemm_kernel<<<dim3(4, 2*(NROWS/128)/4), 256, PRE_SMEM>>>(btd, bh);

    {
        cudaLaunchConfig_t cfg = {};
        cfg.gridDim = dim3((NB/128)*4, 1, 1);   // 128 CTAs = 32 clusters of 4
        cfg.blockDim = dim3(128, 1, 1);
        cfg.dynamicSmemBytes = REC_SMEM;
        cfg.stream = 0;
        cudaLaunchAttribute attr[1];
        attr[0].id = cudaLaunchAttributeClusterDimension;
        attr[0].val.clusterDim.x = 4;
        attr[0].val.clusterDim.y = 1;
        attr[0].val.clusterDim.z = 1;
        cfg.attrs = attr;
        cfg.numAttrs = 1;
        cudaLaunchKernelEx(&cfg, rec_kernel, out);
    }
}

// round 16
// speedup vs baseline: 1.1083x; 1.1083x over previous
#include <cuda_runtime.h>
#include <cuda_fp16.h>
#include <cstdint>
#include <cstddef>

#define NB 4096
#define NT 48
#define NI 128
#define NH 512
#define NROWS (NT*NB)   // 196608

// ---------------- static scratch (allocation-free rule) ----------------
__device__ __half g_D16 [(size_t)NROWS*NI];
__device__ __half g_XM16[(size_t)NROWS*NI];
__device__ __half g_WtdT[NI*NH];
__device__ __half g_U16 [NI*NH];
__device__ __half g_Wh16[NH*NH];
__device__ __half g_G16 [(size_t)NROWS*NH];
__device__ __half g_Z16 [(size_t)NROWS*NH];
__device__ __half g_stage[(size_t)2*32*128*NH];   // double-buffered h*gamma exchange

// ---------------- PTX helpers (sm_103 baseline features only) ----------------
__device__ __forceinline__ void cp16(uint32_t s, const void* g) {
    asm volatile("cp.async.cg.shared.global [%0], [%1], 16;\n" :: "r"(s), "l"(g));
}
__device__ __forceinline__ void cpcommit() { asm volatile("cp.async.commit_group;\n" ::: "memory"); }

__device__ __forceinline__ void ldm4(uint32_t* d, uint32_t a) {
    asm volatile("ldmatrix.sync.aligned.m8n8.x4.shared.b16 {%0,%1,%2,%3}, [%4];\n"
        : "=r"(d[0]), "=r"(d[1]), "=r"(d[2]), "=r"(d[3]) : "r"(a));
}
__device__ __forceinline__ void ldm4t(uint32_t* d, uint32_t a) {
    asm volatile("ldmatrix.sync.aligned.m8n8.x4.trans.shared.b16 {%0,%1,%2,%3}, [%4];\n"
        : "=r"(d[0]), "=r"(d[1]), "=r"(d[2]), "=r"(d[3]) : "r"(a));
}
__device__ __forceinline__ void mma16816(float* c, const uint32_t* a, uint32_t b0, uint32_t b1) {
    asm volatile("mma.sync.aligned.m16n8k16.row.col.f32.f16.f16.f32 "
        "{%0,%1,%2,%3}, {%4,%5,%6,%7}, {%8,%9}, {%0,%1,%2,%3};\n"
        : "+f"(c[0]), "+f"(c[1]), "+f"(c[2]), "+f"(c[3])
        : "r"(a[0]), "r"(a[1]), "r"(a[2]), "r"(a[3]), "r"(b0), "r"(b1));
}
#define CARRIVE() asm volatile("barrier.cluster.arrive.aligned;" ::: "memory")
#define CWAIT()   asm volatile("barrier.cluster.wait.aligned;"   ::: "memory")

// ---------------- weight conversion ----------------
__global__ void convert_weights(const float* __restrict__ Wtd, const float* __restrict__ Wh,
                                const float* __restrict__ Uh) {
    int idx = blockIdx.x*blockDim.x + threadIdx.x;
    if (idx < NI*NH) {
        int i = idx / NH, j = idx % NH;
        g_WtdT[idx] = __float2half_rn(Wtd[j*NI + i]);
        g_U16[idx]  = __float2half_rn(Uh[idx]);
    }
    if (idx < NH*NH) g_Wh16[idx] = __float2half_rn(Wh[idx]);
}

// ---------------- D scan + masked x ----------------
__global__ void dscan_kernel(const float* __restrict__ X, const float* __restrict__ M) {
    int idx = blockIdx.x*blockDim.x + threadIdx.x;
    int b = idx >> 7, i = idx & 127;
    const float* Xp = X + (size_t)b*NT*NI + i;
    const float* Mp = M + (size_t)b*NT*NI + i;
    size_t o = (size_t)b*NI + i;
    float d = 0.f;
    #pragma unroll 1
    for (int t = 0; t < NT; t++) {
        g_D16[(size_t)t*NB*NI + o] = __float2half_rn(d);
        float m = Mp[(size_t)t*NI];
        float x = Xp[(size_t)t*NI];
        g_XM16[(size_t)t*NB*NI + o] = __float2half_rn(m*x);
        d = 1.f + ((m != 1.f) ? d : 0.f);
    }
}

// ---------------- precompute GEMM: B-persistent, smem-staged coalesced output ----------------
// smem: B 32KB + A 2x32KB + out staging 34KB = 133120
#define PG_ROW 136   // 128 halfs + 8 pad (272B rows, conflict-free)
#define PRE_SMEM (98304 + 128*PG_ROW*2)
__global__ __launch_bounds__(256) void pregemm_kernel(const float* __restrict__ b_td,
                                                      const float* __restrict__ b_h) {
    extern __shared__ __half smem[];
    const int tid = threadIdx.x, lane = tid & 31, warp = tid >> 5;
    const int wm = warp & 1, wn = warp >> 1;
    const int n0 = blockIdx.x * 128;
    int yy = blockIdx.y;
    const bool isZ = yy >= (NROWS/128/4);
    if (isZ) yy -= (NROWS/128/4);
    // gamma rows for t=0 multiply h_0 = 0 — never read. Skip those CTAs.
    if (!isZ && yy < 8) return;
    const int base = yy * 4;
    const __half* A  = isZ ? g_XM16 : g_D16;
    const __half* Bm = isZ ? g_U16  : g_WtdT;
    __half* Om = isZ ? g_Z16 : g_G16;
    const float* bias = isZ ? b_h : b_td;

    uint32_t sB  = (uint32_t)__cvta_generic_to_shared(smem);
    uint32_t sA0 = sB + 32768;
    uint32_t sS  = sB + 98304;                 // output staging [128][PG_ROW]

    #pragma unroll
    for (int p = 0; p < 8; p++) {
        int idx = tid + p*256;
        int r = idx >> 4, c = idx & 15;
        cp16(sB + (uint32_t)(r*16 + (c ^ (r & 7)))*16, Bm + (size_t)r*NH + n0 + c*8);
    }
    cpcommit();
    #pragma unroll
    for (int j = 0; j < 2; j++) {
        int row0 = (base + j) * 128;
        #pragma unroll
        for (int p = 0; p < 8; p++) {
            int idx = tid + p*256;
            int r = idx >> 4, c = idx & 15;
            cp16(sA0 + (uint32_t)(j*32768) + (uint32_t)(r*16 + (c ^ (r & 7)))*16,
                 A + (size_t)(row0 + r)*NI + c*8);
        }
        cpcommit();
    }

    #pragma unroll 1
    for (int mb = 0; mb < 4; mb++) {
        const int row0 = (base + mb) * 128;
        if (mb < 3) asm volatile("cp.async.wait_group 1;" ::: "memory");
        else        asm volatile("cp.async.wait_group 0;" ::: "memory");
        __syncthreads();   // A[mb] ready; also: staging reads of mb-1 complete (WAR)
        uint32_t sA = sA0 + (uint32_t)((mb & 1)*32768);

        float acc[4][4][4];
        #pragma unroll
        for (int mt = 0; mt < 4; mt++)
            #pragma unroll
            for (int nt = 0; nt < 4; nt++)
                #pragma unroll
                for (int q = 0; q < 4; q++) acc[mt][nt][q] = 0.f;

        #pragma unroll
        for (int kk = 0; kk < 8; kk++) {
            uint32_t a[4][4];
            #pragma unroll
            for (int mt = 0; mt < 4; mt++) {
                int r = wm*64 + mt*16 + (lane & 15);
                int c = kk*2 + (lane >> 4);
                ldm4(a[mt], sA + (uint32_t)(r*16 + (c ^ (r & 7)))*16);
            }
            uint32_t bf[2][4];
            #pragma unroll
            for (int n2 = 0; n2 < 2; n2++) {
                int g = lane >> 3;
                int r = kk*16 + (g & 1)*8 + (lane & 7);
                int c = wn*4 + n2*2 + (g >> 1);
                ldm4t(bf[n2], sB + (uint32_t)(r*16 + (c ^ (r & 7)))*16);
            }
            #pragma unroll
            for (int mt = 0; mt < 4; mt++)
                #pragma unroll
                for (int nt = 0; nt < 4; nt++)
                    mma16816(acc[mt][nt], a[mt], bf[nt>>1][(nt&1)*2], bf[nt>>1][(nt&1)*2+1]);
        }
        __syncthreads();   // all warps done reading this A buffer

        if (mb + 2 < 4) {
            int row2 = (base + mb + 2) * 128;
            #pragma unroll
            for (int p = 0; p < 8; p++) {
                int idx = tid + p*256;
                int r = idx >> 4, c = idx & 15;
                cp16(sA + (uint32_t)(r*16 + (c ^ (r & 7)))*16,
                     A + (size_t)(row2 + r)*NI + c*8);
            }
            cpcommit();
        }

        // epilogue: compute + STS into staging (conflict-free), then coalesced STG
        #pragma unroll
        for (int mt = 0; mt < 4; mt++) {
            #pragma unroll
            for (int nt = 0; nt < 4; nt++) {
                int col = wn*32 + nt*8 + (lane & 3)*2;           // local col 0..127
                float bv0 = bias[n0 + col], bv1 = bias[n0 + col + 1];
                #pragma unroll
                for (int hh = 0; hh < 2; hh++) {
                    int r = wm*64 + mt*16 + (lane >> 2) + hh*8;  // local row 0..127
                    float v0 = acc[mt][nt][hh*2+0] + bv0;
                    float v1 = acc[mt][nt][hh*2+1] + bv1;
                    if (!isZ) {
                        v0 = __expf(-fmaxf(v0, 0.f));
                        v1 = __expf(-fmaxf(v1, 0.f));
                    }
                    __half2 hv = __floats2half2_rn(v0, v1);
                    asm volatile("st.shared.b32 [%0], %1;"
                        :: "r"(sS + (uint32_t)((r*PG_ROW + col)*2)),
                           "r"(*reinterpret_cast<uint32_t*>(&hv)));
                }
            }
        }
        __syncthreads();   // staging complete
        // coalesced 16B stores: 2048 chunks, 256B contiguous per row
        __half* op = Om + (size_t)row0*NH + n0;
        #pragma unroll
        for (int p = 0; p < 8; p++) {
            int idx = tid + p*256;
            int r = idx >> 4, c = idx & 15;
            uint4 v;
            asm volatile("ld.shared.v4.b32 {%0,%1,%2,%3}, [%4];"
                : "=r"(v.x), "=r"(v.y), "=r"(v.z), "=r"(v.w)
                : "r"(sS + (uint32_t)((r*PG_ROW + c*8)*2)));
            *reinterpret_cast<uint4*>(&op[(size_t)r*NH + c*8]) = v;
        }
        // next iteration's top __syncthreads protects staging WAR
    }
}

// ---------------- recurrent kernel: R13 (best measured: 495us) ----------------
#define SZ_ROW 272
#define REC_SMEM (131072 + 65536 + 128*SZ_ROW)   // 231424

__global__ __launch_bounds__(256, 1) __cluster_dims__(4, 1, 1)
void rec_kernel(float* __restrict__ out) {
    extern __shared__ __half smem[];
    uint32_t sW = (uint32_t)__cvta_generic_to_shared(smem);   // [512][16 chunks] swizzled
    uint32_t sA = sW + 131072;                                // 4 stages x [128][8 chunks]
    uint32_t sZ = sW + 131072 + 65536;                        // [128][272B]

    const int tid = threadIdx.x, lane = tid & 31, warp = tid >> 5;
    const int wm = warp & 3, wn = warp >> 2;      // 4 rowg x 2 colg, 32x64 tiles
    uint32_t rank; asm("mov.u32 %0, %%cluster_ctarank;" : "=r"(rank));
    const int cl = blockIdx.x >> 2;
    const int b0 = cl * 128;
    const int n_base = (int)rank * 128;

    // resident W
    #pragma unroll
    for (int p = 0; p < 32; p++) {
        int idx = tid + p*256;
        int r = idx >> 4, c = idx & 15;
        cp16(sW + (uint32_t)(r*16 + (c ^ (r & 7)))*16,
             g_Wh16 + (size_t)r*NH + n_base + c*8);
    }
    cpcommit();
    asm volatile("cp.async.wait_group 0;" ::: "memory");
    __syncthreads();

    #pragma unroll 1
    for (int t = 0; t < NT; t++) {
        float acc[2][8][4];
        #pragma unroll
        for (int mt = 0; mt < 2; mt++)
            #pragma unroll
            for (int nt = 0; nt < 8; nt++)
                #pragma unroll
                for (int q = 0; q < 4; q++) acc[mt][nt][q] = 0.f;

        uint32_t greg[2][8][2];   // G[t+1] fragments, prefetched early

        if (t) {
            const __half* stg = g_stage + ((size_t)(t & 1)*32 + cl)*128*NH;

            // prefetch A slabs 0..2 (1024 chunks each)
            #pragma unroll
            for (int j = 0; j < 3; j++) {
                #pragma unroll
                for (int p = 0; p < 4; p++) {
                    int idx = tid + p*256;
                    int r = idx >> 3, c = idx & 7;
                    cp16(sA + (uint32_t)(j*16384) + (uint32_t)(r*8 + (c ^ (r & 7)))*16,
                         stg + (size_t)r*NH + j*64 + c*8);
                }
                cpcommit();
            }
            // prefetch Z[t] (2048 chunks)
            {
                const __half* zsrc = g_Z16 + ((size_t)t*NB + b0)*NH + n_base;
                #pragma unroll
                for (int p = 0; p < 8; p++) {
                    int idx = tid + p*256;
                    int r = idx >> 4, c = idx & 15;
                    cp16(sZ + (uint32_t)(r*SZ_ROW + c*16), zsrc + (size_t)r*NH + c*8);
                }
                cpcommit();
            }
            // early G[t+1] prefetch: latency hides under the MMA ladder
            if (t + 1 < NT) {
                #pragma unroll
                for (int mt = 0; mt < 2; mt++)
                    #pragma unroll
                    for (int hh = 0; hh < 2; hh++) {
                        int row = wm*32 + mt*16 + (lane >> 2) + hh*8;
                        size_t grow = ((size_t)(t+1)*NB + b0 + row)*NH;
                        #pragma unroll
                        for (int nt = 0; nt < 8; nt++) {
                            int gcol = n_base + wn*64 + nt*8 + (lane & 3)*2;
                            greg[mt][nt][hh] =
                                __ldg(reinterpret_cast<const uint32_t*>(&g_G16[grow + gcol]));
                        }
                    }
            }

            #pragma unroll
            for (int s = 0; s < 8; s++) {
                if (s < 3)       asm volatile("cp.async.wait_group 3;" ::: "memory");
                else if (s < 6)  asm volatile("cp.async.wait_group 2;" ::: "memory");
                else if (s == 6) asm volatile("cp.async.wait_group 1;" ::: "memory");
                else             asm volatile("cp.async.wait_group 0;" ::: "memory");
                __syncthreads();
                if (s < 5) {                 // refill slab s+3 into stage (s+3)&3
                    int j = s + 3;
                    #pragma unroll
                    for (int p = 0; p < 4; p++) {
                        int idx = tid + p*256;
                        int r = idx >> 3, c = idx & 7;
                        cp16(sA + (uint32_t)((j & 3)*16384) + (uint32_t)(r*8 + (c ^ (r & 7)))*16,
                             stg + (size_t)r*NH + j*64 + c*8);
                    }
                    cpcommit();
                }
                uint32_t bufA = sA + (uint32_t)((s & 3)*16384);
                // batched fragment loads in k16-pairs: 8 LDSMs back-to-back (MLP)
                #pragma unroll
                for (int kp = 0; kp < 2; kp++) {
                    uint32_t a[2][2][4];
                    uint32_t bf[2][4][4];
                    #pragma unroll
                    for (int kq = 0; kq < 2; kq++) {
                        int k16 = kp*2 + kq;
                        #pragma unroll
                        for (int mt = 0; mt < 2; mt++) {
                            int r = wm*32 + mt*16 + (lane & 15);
                            int c = k16*2 + (lane >> 4);
                            ldm4(a[kq][mt], bufA + (uint32_t)(r*8 + (c ^ (r & 7)))*16);
                        }
                        int gq = lane >> 3;
                        #pragma unroll
                        for (int n2 = 0; n2 < 4; n2++) {
                            int rr = s*64 + k16*16 + (gq & 1)*8 + (lane & 7);
                            int c = wn*8 + n2*2 + (gq >> 1);
                            ldm4t(bf[kq][n2], sW + (uint32_t)(rr*16 + (c ^ (rr & 7)))*16);
                        }
                    }
                    #pragma unroll
                    for (int kq = 0; kq < 2; kq++)
                        #pragma unroll
                        for (int mt = 0; mt < 2; mt++)
                            #pragma unroll
                            for (int nt = 0; nt < 8; nt++)
                                mma16816(acc[mt][nt], a[kq][mt],
                                         bf[kq][nt>>1][(nt&1)*2], bf[kq][nt>>1][(nt&1)*2+1]);
                }
            }
        } else {
            // t==0: Z prefetch + early G[1]
            const __half* zsrc = g_Z16 + ((size_t)b0)*NH + n_base;
            #pragma unroll
            for (int p = 0; p < 8; p++) {
                int idx = tid + p*256;
                int r = idx >> 4, c = idx & 15;
                cp16(sZ + (uint32_t)(r*SZ_ROW + c*16), zsrc + (size_t)r*NH + c*8);
            }
            cpcommit();
            #pragma unroll
            for (int mt = 0; mt < 2; mt++)
                #pragma unroll
                for (int hh = 0; hh < 2; hh++) {
                    int row = wm*32 + mt*16 + (lane >> 2) + hh*8;
                    size_t grow = ((size_t)NB + b0 + row)*NH;
                    #pragma unroll
                    for (int nt = 0; nt < 8; nt++) {
                        int gcol = n_base + wn*64 + nt*8 + (lane & 3)*2;
                        greg[mt][nt][hh] =
                            __ldg(reinterpret_cast<const uint32_t*>(&g_G16[grow + gcol]));
                    }
                }
            asm volatile("cp.async.wait_group 0;" ::: "memory");
            __syncthreads();
        }

        // ---- epilogue: h = sigmoid(acc + Z_smem); STG out; STS h*gamma into sZ ----
        #pragma unroll
        for (int mt = 0; mt < 2; mt++) {
            #pragma unroll
            for (int hh = 0; hh < 2; hh++) {
                int row = wm*32 + mt*16 + (lane >> 2) + hh*8;
                size_t orow = ((size_t)(b0 + row)*NT + t)*NH;
                #pragma unroll
                for (int nt = 0; nt < 8; nt++) {
                    int col = wn*64 + nt*8 + (lane & 3)*2;      // local col (0..127)
                    uint32_t zaddr = sZ + (uint32_t)(row*SZ_ROW + col*2);
                    uint32_t zu;
                    asm volatile("ld.shared.b32 %0, [%1];" : "=r"(zu) : "r"(zaddr));
                    float2 z = __half22float2(*reinterpret_cast<__half2*>(&zu));
                    float s0 = acc[mt][nt][hh*2+0] + z.x;
                    float s1 = acc[mt][nt][hh*2+1] + z.y;
                    float t0, t1;
                    asm("tanh.approx.f32 %0, %1;" : "=f"(t0) : "f"(s0*0.5f));
                    asm("tanh.approx.f32 %0, %1;" : "=f"(t1) : "f"(s1*0.5f));
                    float h0 = fmaf(0.5f, t0, 0.5f);
                    float h1 = fmaf(0.5f, t1, 0.5f);
                    *reinterpret_cast<float2*>(&out[orow + n_base + col]) = make_float2(h0, h1);
                    if (t + 1 < NT) {
                        uint32_t gu = greg[mt][nt][hh];
                        float2 gf = __half22float2(*reinterpret_cast<__half2*>(&gu));
                        __half2 v = __floats2half2_rn(h0*gf.x, h1*gf.y);
                        asm volatile("st.shared.b32 [%0], %1;"
                                     :: "r"(zaddr), "r"(*reinterpret_cast<uint32_t*>(&v)));
                    }
                }
            }
        }

        if (t + 1 < NT) {
            __syncthreads();   // all STS visible
            // coalesced copy sZ -> stage[(t+1)&1] (2048 x 16B)
            __half* stw = g_stage + ((size_t)((t + 1) & 1)*32 + cl)*128*NH + n_base;
            #pragma unroll
            for (int p = 0; p < 8; p++) {
                int chunk = tid + p*256;
                int r = chunk >> 4, c = chunk & 15;
                uint4 v;
                asm volatile("ld.shared.v4.b32 {%0,%1,%2,%3}, [%4];"
                    : "=r"(v.x), "=r"(v.y), "=r"(v.z), "=r"(v.w)
                    : "r"(sZ + (uint32_t)(r*SZ_ROW + c*16)));
                __stcg(reinterpret_cast<uint4*>(&stw[(size_t)r*NH + c*8]), v);
            }
            CARRIVE();
            CWAIT();
        }
        __syncthreads();
    }
}

// ---------------- launch ----------------
extern "C" void kernel_launch(void* const* d_in, const int* in_sizes, int n_in,
                              void* d_out, int out_size) {
    const float* X   = (const float*)d_in[0];
    const float* M   = (const float*)d_in[1];
    const float* Wtd = (const float*)d_in[2];
    const float* btd = (const float*)d_in[3];
    // d_in[4] = W_hr, d_in[5] = b_hr : provably dead (m binary => x_c*m == m*x)
    const float* Wh  = (const float*)d_in[6];
    const float* Uh  = (const float*)d_in[7];
    const float* bh  = (const float*)d_in[8];
    float* out = (float*)d_out;

    cudaFuncSetAttribute(pregemm_kernel, cudaFuncAttributeMaxDynamicSharedMemorySize, PRE_SMEM);
    cudaFuncSetAttribute(rec_kernel,     cudaFuncAttributeMaxDynamicSharedMemorySize, REC_SMEM);

    convert_weights<<<1024, 256>>>(Wtd, Wh, Uh);
    dscan_kernel<<<(NB*NI)/256, 256>>>(X, M);
    pregemm_kernel<<<dim3(4, 2*(NROWS/128)/4), 256, PRE_SMEM>>>(btd, bh);

    {
        cudaLaunchConfig_t cfg = {};
        cfg.gridDim = dim3((NB/128)*4, 1, 1);   // 128 CTAs = 32 clusters of 4
        cfg.blockDim = dim3(256, 1, 1);
        cfg.dynamicSmemBytes = REC_SMEM;
        cfg.stream = 0;
        cudaLaunchAttribute attr[1];
        attr[0].id = cudaLaunchAttributeClusterDimension;
        attr[0].val.clusterDim.x = 4;
        attr[0].val.clusterDim.y = 1;
        attr[0].val.clusterDim.z = 1;
        cfg.attrs = attr;
        cfg.numAttrs = 1;
        cudaLaunchKernelEx(&cfg, rec_kernel, out);
    }
}

// round 17
// speedup vs baseline: 1.1892x; 1.0730x over previous
#include <cuda_runtime.h>
#include <cuda_fp16.h>
#include <cstdint>
#include <cstddef>

#define NB 4096
#define NT 48
#define NI 128
#define NH 512
#define NROWS (NT*NB)   // 196608

// ---------------- static scratch (allocation-free rule) ----------------
__device__ __half g_D16 [(size_t)NROWS*NI];
__device__ __half g_XM16[(size_t)NROWS*NI];
__device__ __half g_WtdT[NI*NH];
__device__ __half g_U16 [NI*NH];
__device__ __half g_Wh16[NH*NH];
__device__ __half g_G16 [(size_t)NROWS*NH];
__device__ __half g_Z16 [(size_t)NROWS*NH];
__device__ __half g_stage[(size_t)2*32*128*NH];   // double-buffered h*gamma exchange

// ---------------- PTX helpers (sm_103 baseline features only) ----------------
__device__ __forceinline__ void cp16(uint32_t s, const void* g) {
    asm volatile("cp.async.cg.shared.global [%0], [%1], 16;\n" :: "r"(s), "l"(g));
}
__device__ __forceinline__ void cpcommit() { asm volatile("cp.async.commit_group;\n" ::: "memory"); }

__device__ __forceinline__ void ldm4(uint32_t* d, uint32_t a) {
    asm volatile("ldmatrix.sync.aligned.m8n8.x4.shared.b16 {%0,%1,%2,%3}, [%4];\n"
        : "=r"(d[0]), "=r"(d[1]), "=r"(d[2]), "=r"(d[3]) : "r"(a));
}
__device__ __forceinline__ void ldm4t(uint32_t* d, uint32_t a) {
    asm volatile("ldmatrix.sync.aligned.m8n8.x4.trans.shared.b16 {%0,%1,%2,%3}, [%4];\n"
        : "=r"(d[0]), "=r"(d[1]), "=r"(d[2]), "=r"(d[3]) : "r"(a));
}
__device__ __forceinline__ void mma16816(float* c, const uint32_t* a, uint32_t b0, uint32_t b1) {
    asm volatile("mma.sync.aligned.m16n8k16.row.col.f32.f16.f16.f32 "
        "{%0,%1,%2,%3}, {%4,%5,%6,%7}, {%8,%9}, {%0,%1,%2,%3};\n"
        : "+f"(c[0]), "+f"(c[1]), "+f"(c[2]), "+f"(c[3])
        : "r"(a[0]), "r"(a[1]), "r"(a[2]), "r"(a[3]), "r"(b0), "r"(b1));
}
#define CARRIVE() asm volatile("barrier.cluster.arrive.aligned;" ::: "memory")
#define CWAIT()   asm volatile("barrier.cluster.wait.aligned;"   ::: "memory")

// ---------------- fused D scan + masked x + weight conversion ----------------
// blocks [0, 2048): dscan (4096*128 threads). blocks [2048, 3072+1024): weights.
__global__ void prep_kernel(const float* __restrict__ X, const float* __restrict__ M,
                            const float* __restrict__ Wtd, const float* __restrict__ Wh,
                            const float* __restrict__ Uh) {
    int blk = blockIdx.x;
    if (blk < 2048) {
        int idx = blk*blockDim.x + threadIdx.x;   // b*128 + i
        int b = idx >> 7, i = idx & 127;
        const float* Xp = X + (size_t)b*NT*NI + i;
        const float* Mp = M + (size_t)b*NT*NI + i;
        size_t o = (size_t)b*NI + i;
        float d = 0.f;
        #pragma unroll 1
        for (int t = 0; t < NT; t++) {
            g_D16[(size_t)t*NB*NI + o] = __float2half_rn(d);
            float m = Mp[(size_t)t*NI];
            float x = Xp[(size_t)t*NI];
            g_XM16[(size_t)t*NB*NI + o] = __float2half_rn(m*x);
            d = 1.f + ((m != 1.f) ? d : 0.f);
        }
    } else {
        int idx = (blk - 2048)*blockDim.x + threadIdx.x;
        if (idx < NI*NH) {
            int i = idx / NH, j = idx % NH;
            g_WtdT[idx] = __float2half_rn(Wtd[j*NI + i]);
            g_U16[idx]  = __float2half_rn(Uh[idx]);
        }
        if (idx < NH*NH) g_Wh16[idx] = __float2half_rn(Wh[idx]);
    }
}

// ---------------- precompute GEMM: B-persistent, 4 m-blocks per CTA ----------------
#define PRE_SMEM 98304
__global__ __launch_bounds__(256) void pregemm_kernel(const float* __restrict__ b_td,
                                                      const float* __restrict__ b_h) {
    extern __shared__ __half smem[];
    const int tid = threadIdx.x, lane = tid & 31, warp = tid >> 5;
    const int wm = warp & 1, wn = warp >> 1;
    const int n0 = blockIdx.x * 128;
    int yy = blockIdx.y;
    const bool isZ = yy >= (NROWS/128/4);
    if (isZ) yy -= (NROWS/128/4);
    // gamma rows for t=0 multiply h_0 = 0 — never read. Skip those CTAs.
    if (!isZ && yy < 8) return;
    const int base = yy * 4;
    const __half* A  = isZ ? g_XM16 : g_D16;
    const __half* Bm = isZ ? g_U16  : g_WtdT;
    const float* bias = isZ ? b_h : b_td;

    uint32_t sB  = (uint32_t)__cvta_generic_to_shared(smem);
    uint32_t sA0 = sB + 32768;

    #pragma unroll
    for (int p = 0; p < 8; p++) {
        int idx = tid + p*256;
        int r = idx >> 4, c = idx & 15;
        cp16(sB + (uint32_t)(r*16 + (c ^ (r & 7)))*16, Bm + (size_t)r*NH + n0 + c*8);
    }
    cpcommit();
    #pragma unroll
    for (int j = 0; j < 2; j++) {
        int row0 = (base + j) * 128;
        #pragma unroll
        for (int p = 0; p < 8; p++) {
            int idx = tid + p*256;
            int r = idx >> 4, c = idx & 15;
            cp16(sA0 + (uint32_t)(j*32768) + (uint32_t)(r*16 + (c ^ (r & 7)))*16,
                 A + (size_t)(row0 + r)*NI + c*8);
        }
        cpcommit();
    }

    #pragma unroll 1
    for (int mb = 0; mb < 4; mb++) {
        const int row0 = (base + mb) * 128;
        if (mb < 3) asm volatile("cp.async.wait_group 1;" ::: "memory");
        else        asm volatile("cp.async.wait_group 0;" ::: "memory");
        __syncthreads();
        uint32_t sA = sA0 + (uint32_t)((mb & 1)*32768);

        float acc[4][4][4];
        #pragma unroll
        for (int mt = 0; mt < 4; mt++)
            #pragma unroll
            for (int nt = 0; nt < 4; nt++)
                #pragma unroll
                for (int q = 0; q < 4; q++) acc[mt][nt][q] = 0.f;

        #pragma unroll
        for (int kk = 0; kk < 8; kk++) {
            uint32_t a[4][4];
            #pragma unroll
            for (int mt = 0; mt < 4; mt++) {
                int r = wm*64 + mt*16 + (lane & 15);
                int c = kk*2 + (lane >> 4);
                ldm4(a[mt], sA + (uint32_t)(r*16 + (c ^ (r & 7)))*16);
            }
            uint32_t bf[2][4];
            #pragma unroll
            for (int n2 = 0; n2 < 2; n2++) {
                int g = lane >> 3;
                int r = kk*16 + (g & 1)*8 + (lane & 7);
                int c = wn*4 + n2*2 + (g >> 1);
                ldm4t(bf[n2], sB + (uint32_t)(r*16 + (c ^ (r & 7)))*16);
            }
            #pragma unroll
            for (int mt = 0; mt < 4; mt++)
                #pragma unroll
                for (int nt = 0; nt < 4; nt++)
                    mma16816(acc[mt][nt], a[mt], bf[nt>>1][(nt&1)*2], bf[nt>>1][(nt&1)*2+1]);
        }
        __syncthreads();

        if (mb + 2 < 4) {
            int row2 = (base + mb + 2) * 128;
            #pragma unroll
            for (int p = 0; p < 8; p++) {
                int idx = tid + p*256;
                int r = idx >> 4, c = idx & 15;
                cp16(sA + (uint32_t)(r*16 + (c ^ (r & 7)))*16,
                     A + (size_t)(row2 + r)*NI + c*8);
            }
            cpcommit();
        }

        #pragma unroll
        for (int mt = 0; mt < 4; mt++) {
            #pragma unroll
            for (int nt = 0; nt < 4; nt++) {
                int col = n0 + wn*32 + nt*8 + (lane & 3)*2;
                float bv0 = bias[col], bv1 = bias[col+1];
                #pragma unroll
                for (int hh = 0; hh < 2; hh++) {
                    int r = row0 + wm*64 + mt*16 + (lane >> 2) + hh*8;
                    float v0 = acc[mt][nt][hh*2+0] + bv0;
                    float v1 = acc[mt][nt][hh*2+1] + bv1;
                    if (!isZ) {
                        v0 = __expf(-fmaxf(v0, 0.f));
                        v1 = __expf(-fmaxf(v1, 0.f));
                        *reinterpret_cast<__half2*>(&g_G16[(size_t)r*NH + col]) = __floats2half2_rn(v0, v1);
                    } else {
                        *reinterpret_cast<__half2*>(&g_Z16[(size_t)r*NH + col]) = __floats2half2_rn(v0, v1);
                    }
                }
            }
        }
    }
}

// ---------------- recurrent kernel: R13 (best measured: 495us) ----------------
#define SZ_ROW 272
#define REC_SMEM (131072 + 65536 + 128*SZ_ROW)   // 231424

__global__ __launch_bounds__(256, 1) __cluster_dims__(4, 1, 1)
void rec_kernel(float* __restrict__ out) {
    extern __shared__ __half smem[];
    uint32_t sW = (uint32_t)__cvta_generic_to_shared(smem);   // [512][16 chunks] swizzled
    uint32_t sA = sW + 131072;                                // 4 stages x [128][8 chunks]
    uint32_t sZ = sW + 131072 + 65536;                        // [128][272B]

    const int tid = threadIdx.x, lane = tid & 31, warp = tid >> 5;
    const int wm = warp & 3, wn = warp >> 2;      // 4 rowg x 2 colg, 32x64 tiles
    uint32_t rank; asm("mov.u32 %0, %%cluster_ctarank;" : "=r"(rank));
    const int cl = blockIdx.x >> 2;
    const int b0 = cl * 128;
    const int n_base = (int)rank * 128;

    // resident W
    #pragma unroll
    for (int p = 0; p < 32; p++) {
        int idx = tid + p*256;
        int r = idx >> 4, c = idx & 15;
        cp16(sW + (uint32_t)(r*16 + (c ^ (r & 7)))*16,
             g_Wh16 + (size_t)r*NH + n_base + c*8);
    }
    cpcommit();
    asm volatile("cp.async.wait_group 0;" ::: "memory");
    __syncthreads();

    #pragma unroll 1
    for (int t = 0; t < NT; t++) {
        float acc[2][8][4];
        #pragma unroll
        for (int mt = 0; mt < 2; mt++)
            #pragma unroll
            for (int nt = 0; nt < 8; nt++)
                #pragma unroll
                for (int q = 0; q < 4; q++) acc[mt][nt][q] = 0.f;

        uint32_t greg[2][8][2];   // G[t+1] fragments, prefetched early

        if (t) {
            const __half* stg = g_stage + ((size_t)(t & 1)*32 + cl)*128*NH;

            // prefetch A slabs 0..2 (1024 chunks each)
            #pragma unroll
            for (int j = 0; j < 3; j++) {
                #pragma unroll
                for (int p = 0; p < 4; p++) {
                    int idx = tid + p*256;
                    int r = idx >> 3, c = idx & 7;
                    cp16(sA + (uint32_t)(j*16384) + (uint32_t)(r*8 + (c ^ (r & 7)))*16,
                         stg + (size_t)r*NH + j*64 + c*8);
                }
                cpcommit();
            }
            // prefetch Z[t] (2048 chunks)
            {
                const __half* zsrc = g_Z16 + ((size_t)t*NB + b0)*NH + n_base;
                #pragma unroll
                for (int p = 0; p < 8; p++) {
                    int idx = tid + p*256;
                    int r = idx >> 4, c = idx & 15;
                    cp16(sZ + (uint32_t)(r*SZ_ROW + c*16), zsrc + (size_t)r*NH + c*8);
                }
                cpcommit();
            }
            // early G[t+1] prefetch: latency hides under the MMA ladder
            if (t + 1 < NT) {
                #pragma unroll
                for (int mt = 0; mt < 2; mt++)
                    #pragma unroll
                    for (int hh = 0; hh < 2; hh++) {
                        int row = wm*32 + mt*16 + (lane >> 2) + hh*8;
                        size_t grow = ((size_t)(t+1)*NB + b0 + row)*NH;
                        #pragma unroll
                        for (int nt = 0; nt < 8; nt++) {
                            int gcol = n_base + wn*64 + nt*8 + (lane & 3)*2;
                            greg[mt][nt][hh] =
                                __ldg(reinterpret_cast<const uint32_t*>(&g_G16[grow + gcol]));
                        }
                    }
            }

            #pragma unroll
            for (int s = 0; s < 8; s++) {
                if (s < 3)       asm volatile("cp.async.wait_group 3;" ::: "memory");
                else if (s < 6)  asm volatile("cp.async.wait_group 2;" ::: "memory");
                else if (s == 6) asm volatile("cp.async.wait_group 1;" ::: "memory");
                else             asm volatile("cp.async.wait_group 0;" ::: "memory");
                __syncthreads();
                if (s < 5) {                 // refill slab s+3 into stage (s+3)&3
                    int j = s + 3;
                    #pragma unroll
                    for (int p = 0; p < 4; p++) {
                        int idx = tid + p*256;
                        int r = idx >> 3, c = idx & 7;
                        cp16(sA + (uint32_t)((j & 3)*16384) + (uint32_t)(r*8 + (c ^ (r & 7)))*16,
                             stg + (size_t)r*NH + j*64 + c*8);
                    }
                    cpcommit();
                }
                uint32_t bufA = sA + (uint32_t)((s & 3)*16384);
                // batched fragment loads in k16-pairs: 8 LDSMs back-to-back (MLP)
                #pragma unroll
                for (int kp = 0; kp < 2; kp++) {
                    uint32_t a[2][2][4];
                    uint32_t bf[2][4][4];
                    #pragma unroll
                    for (int kq = 0; kq < 2; kq++) {
                        int k16 = kp*2 + kq;
                        #pragma unroll
                        for (int mt = 0; mt < 2; mt++) {
                            int r = wm*32 + mt*16 + (lane & 15);
                            int c = k16*2 + (lane >> 4);
                            ldm4(a[kq][mt], bufA + (uint32_t)(r*8 + (c ^ (r & 7)))*16);
                        }
                        int gq = lane >> 3;
                        #pragma unroll
                        for (int n2 = 0; n2 < 4; n2++) {
                            int rr = s*64 + k16*16 + (gq & 1)*8 + (lane & 7);
                            int c = wn*8 + n2*2 + (gq >> 1);
                            ldm4t(bf[kq][n2], sW + (uint32_t)(rr*16 + (c ^ (rr & 7)))*16);
                        }
                    }
                    #pragma unroll
                    for (int kq = 0; kq < 2; kq++)
                        #pragma unroll
                        for (int mt = 0; mt < 2; mt++)
                            #pragma unroll
                            for (int nt = 0; nt < 8; nt++)
                                mma16816(acc[mt][nt], a[kq][mt],
                                         bf[kq][nt>>1][(nt&1)*2], bf[kq][nt>>1][(nt&1)*2+1]);
                }
            }
        } else {
            // t==0: Z prefetch + early G[1]
            const __half* zsrc = g_Z16 + ((size_t)b0)*NH + n_base;
            #pragma unroll
            for (int p = 0; p < 8; p++) {
                int idx = tid + p*256;
                int r = idx >> 4, c = idx & 15;
                cp16(sZ + (uint32_t)(r*SZ_ROW + c*16), zsrc + (size_t)r*NH + c*8);
            }
            cpcommit();
            #pragma unroll
            for (int mt = 0; mt < 2; mt++)
                #pragma unroll
                for (int hh = 0; hh < 2; hh++) {
                    int row = wm*32 + mt*16 + (lane >> 2) + hh*8;
                    size_t grow = ((size_t)NB + b0 + row)*NH;
                    #pragma unroll
                    for (int nt = 0; nt < 8; nt++) {
                        int gcol = n_base + wn*64 + nt*8 + (lane & 3)*2;
                        greg[mt][nt][hh] =
                            __ldg(reinterpret_cast<const uint32_t*>(&g_G16[grow + gcol]));
                    }
                }
            asm volatile("cp.async.wait_group 0;" ::: "memory");
            __syncthreads();
        }

        // ---- epilogue: h = sigmoid(acc + Z_smem); STG out; STS h*gamma into sZ ----
        #pragma unroll
        for (int mt = 0; mt < 2; mt++) {
            #pragma unroll
            for (int hh = 0; hh < 2; hh++) {
                int row = wm*32 + mt*16 + (lane >> 2) + hh*8;
                size_t orow = ((size_t)(b0 + row)*NT + t)*NH;
                #pragma unroll
                for (int nt = 0; nt < 8; nt++) {
                    int col = wn*64 + nt*8 + (lane & 3)*2;      // local col (0..127)
                    uint32_t zaddr = sZ + (uint32_t)(row*SZ_ROW + col*2);
                    uint32_t zu;
                    asm volatile("ld.shared.b32 %0, [%1];" : "=r"(zu) : "r"(zaddr));
                    float2 z = __half22float2(*reinterpret_cast<__half2*>(&zu));
                    float s0 = acc[mt][nt][hh*2+0] + z.x;
                    float s1 = acc[mt][nt][hh*2+1] + z.y;
                    float t0, t1;
                    asm("tanh.approx.f32 %0, %1;" : "=f"(t0) : "f"(s0*0.5f));
                    asm("tanh.approx.f32 %0, %1;" : "=f"(t1) : "f"(s1*0.5f));
                    float h0 = fmaf(0.5f, t0, 0.5f);
                    float h1 = fmaf(0.5f, t1, 0.5f);
                    *reinterpret_cast<float2*>(&out[orow + n_base + col]) = make_float2(h0, h1);
                    if (t + 1 < NT) {
                        uint32_t gu = greg[mt][nt][hh];
                        float2 gf = __half22float2(*reinterpret_cast<__half2*>(&gu));
                        __half2 v = __floats2half2_rn(h0*gf.x, h1*gf.y);
                        asm volatile("st.shared.b32 [%0], %1;"
                                     :: "r"(zaddr), "r"(*reinterpret_cast<uint32_t*>(&v)));
                    }
                }
            }
        }

        if (t + 1 < NT) {
            __syncthreads();   // all STS visible
            // coalesced copy sZ -> stage[(t+1)&1] (2048 x 16B)
            __half* stw = g_stage + ((size_t)((t + 1) & 1)*32 + cl)*128*NH + n_base;
            #pragma unroll
            for (int p = 0; p < 8; p++) {
                int chunk = tid + p*256;
                int r = chunk >> 4, c = chunk & 15;
                uint4 v;
                asm volatile("ld.shared.v4.b32 {%0,%1,%2,%3}, [%4];"
                    : "=r"(v.x), "=r"(v.y), "=r"(v.z), "=r"(v.w)
                    : "r"(sZ + (uint32_t)(r*SZ_ROW + c*16)));
                __stcg(reinterpret_cast<uint4*>(&stw[(size_t)r*NH + c*8]), v);
            }
            CARRIVE();
            CWAIT();
        }
        __syncthreads();
    }
}

// ---------------- launch ----------------
extern "C" void kernel_launch(void* const* d_in, const int* in_sizes, int n_in,
                              void* d_out, int out_size) {
    const float* X   = (const float*)d_in[0];
    const float* M   = (const float*)d_in[1];
    const float* Wtd = (const float*)d_in[2];
    const float* btd = (const float*)d_in[3];
    // d_in[4] = W_hr, d_in[5] = b_hr : provably dead (m binary => x_c*m == m*x)
    const float* Wh  = (const float*)d_in[6];
    const float* Uh  = (const float*)d_in[7];
    const float* bh  = (const float*)d_in[8];
    float* out = (float*)d_out;

    cudaFuncSetAttribute(pregemm_kernel, cudaFuncAttributeMaxDynamicSharedMemorySize, PRE_SMEM);
    cudaFuncSetAttribute(rec_kernel,     cudaFuncAttributeMaxDynamicSharedMemorySize, REC_SMEM);

    // fused dscan + weight conversion (blocks >= 2048 convert weights)
    prep_kernel<<<2048 + 1024, 256>>>(X, M, Wtd, Wh, Uh);
    pregemm_kernel<<<dim3(4, 2*(NROWS/128)/4), 256, PRE_SMEM>>>(btd, bh);

    {
        cudaLaunchConfig_t cfg = {};
        cfg.gridDim = dim3((NB/128)*4, 1, 1);   // 128 CTAs = 32 clusters of 4
        cfg.blockDim = dim3(256, 1, 1);
        cfg.dynamicSmemBytes = REC_SMEM;
        cfg.stream = 0;
        cudaLaunchAttribute attr[1];
        attr[0].id = cudaLaunchAttributeClusterDimension;
        attr[0].val.clusterDim.x = 4;
        attr[0].val.clusterDim.y = 1;
        attr[0].val.clusterDim.z = 1;
        cfg.attrs = attr;
        cfg.numAttrs = 1;
        cudaLaunchKernelEx(&cfg, rec_kernel, out);
    }
}